// round 2
// baseline (speedup 1.0000x reference)
#include <cuda_runtime.h>

typedef unsigned long long u64;

#define HIDN 10
#define CCH  256
#define HWV  16384
#define NIMG 8
#define NPAIR 65536
// output offsets (floats)
#define OUT_XHL  1310720
#define OUT_ATTU 2621440
#define OUT_ATTL 2752512

// scratch: 22 planes of (pixA,pixB) packed dots, [22][NPAIR] u64 = 11.5 MiB
__device__ u64 g_hacc[22 * NPAIR];

// ---------- packed f32x2 helpers ----------
__device__ __forceinline__ u64 ffma2(u64 a, u64 b, u64 c) {
    u64 d; asm("fma.rn.f32x2 %0,%1,%2,%3;" : "=l"(d) : "l"(a), "l"(b), "l"(c)); return d;
}
__device__ __forceinline__ u64 fmul2(u64 a, u64 b) {
    u64 d; asm("mul.rn.f32x2 %0,%1,%2;" : "=l"(d) : "l"(a), "l"(b)); return d;
}
__device__ __forceinline__ u64 fadd2(u64 a, u64 b) {
    u64 d; asm("add.rn.f32x2 %0,%1,%2;" : "=l"(d) : "l"(a), "l"(b)); return d;
}
__device__ __forceinline__ u64 pack2(float x, float y) {
    u64 d; asm("mov.b64 %0,{%1,%2};" : "=l"(d) : "f"(x), "f"(y)); return d;
}
__device__ __forceinline__ void unpack2(u64 a, float& x, float& y) {
    asm("mov.b64 {%0,%1},%2;" : "=f"(x), "=f"(y) : "l"(a));
}
__device__ __forceinline__ u64 dup2(float x) { return pack2(x, x); }
__device__ __forceinline__ u64 relu2(u64 a) {
    float x, y; unpack2(a, x, y);
    return pack2(fmaxf(x, 0.f), fmaxf(y, 0.f));
}
__device__ __forceinline__ u64 sigmoid2(u64 a) {
    float x, y; unpack2(a, x, y);
    x = __fdividef(1.f, 1.f + __expf(-x));
    y = __fdividef(1.f, 1.f + __expf(-y));
    return pack2(x, y);
}
__device__ __forceinline__ u64 neg2(u64 a) { return a ^ 0x8000000080000000ULL; }

// ============================================================================
// Kernel 1: 22 dots over 256 h_fea channels per pixel-pair.
// acc[j] = (dot_j(pixA), dot_j(pixB)); h loaded as float2 -> u64 used directly.
// ============================================================================

__device__ __forceinline__ void k1comp(u64 (&acc)[22], const u64 (&hv)[8],
                                       const u64* swrow) {
#pragma unroll
    for (int u = 0; u < 8; u++) {
        u64 h2 = hv[u];
        const u64* wr = swrow + u * 22;
#pragma unroll
        for (int j = 0; j < 22; j++) acc[j] = ffma2(h2, wr[j], acc[j]);
    }
}

__global__ void __launch_bounds__(256, 2) k1_kernel(const float* __restrict__ hfea,
                                                    const float* __restrict__ w_pdp1,
                                                    const float* __restrict__ w_dua,
                                                    const float* __restrict__ w_dla) {
    __shared__ u64 sw[256 * 22];   // per-channel 22 dup'd weights, 176B rows (16B aligned)
    const int tid = threadIdx.x;
    for (int i = tid; i < 256 * 22; i += 256) {
        int c = i / 22, j = i % 22;
        float w;
        if (j < 20)       w = w_pdp1[j * 276 + c];
        else if (j == 20) w = w_dua[c];
        else              w = w_dla[c];
        sw[i] = dup2(w);
    }
    __syncthreads();

    const int pair = blockIdx.x * 256 + tid;
    const int pix  = pair * 2;
    const int n    = pix >> 14;
    const int hw   = pix & (HWV - 1);
    const float* hp = hfea + (size_t)n * CCH * HWV + hw;

    u64 acc[22];
#pragma unroll
    for (int j = 0; j < 22; j++) acc[j] = 0ULL;

    u64 hv0[8], hv1[8];
#pragma unroll
    for (int u = 0; u < 8; u++) hv0[u] = *(const u64*)(hp + (size_t)u * HWV);
    const float* hq = hp + (size_t)8 * HWV;   // points at channel group c0+8

#pragma unroll 1
    for (int c0 = 0; c0 < 240; c0 += 16) {
#pragma unroll
        for (int u = 0; u < 8; u++) hv1[u] = *(const u64*)(hq + (size_t)u * HWV);
        k1comp(acc, hv0, sw + c0 * 22);
#pragma unroll
        for (int u = 0; u < 8; u++) hv0[u] = *(const u64*)(hq + (size_t)(8 + u) * HWV);
        k1comp(acc, hv1, sw + (c0 + 8) * 22);
        hq += (size_t)16 * HWV;
    }
    // tail: hv0 = ch 240-247, hq = ch 248
#pragma unroll
    for (int u = 0; u < 8; u++) hv1[u] = *(const u64*)(hq + (size_t)u * HWV);
    k1comp(acc, hv0, sw + 240 * 22);
    k1comp(acc, hv1, sw + 248 * 22);

    u64* gp = g_hacc + pair;
#pragma unroll
    for (int j = 0; j < 22; j++) gp[(size_t)j * NPAIR] = acc[j];
}

// ============================================================================
// Kernel 2: HID=10 graph ops, packed over the pixel pair.
// ============================================================================

struct P27 {
    const float* a[27];
    float* out;
};

// s_small offsets (u64 units), all values duplicated (w,w)
// 0    : pdp_w1 tail [o*20+k] (400)
// 400  : pdp_w2 flat (200)
// 600  : att_w (20), 620: att_b (2)
// 622  : compU_att_w (40), 662: compU_att_b (4), 666: compU_w (200)
// 866  : compL_att_w (20), 886: compL_att_b (2), 888: compL_w (200)
// 1088 : decU_att tail (20), 1108: decU_att_b (1), 1109: decU_w (100)
// 1209 : decL_att tail (20), 1229: decL_att_b (1), 1230: decL_w (100)
// 1330 : updU_gate_w (200), 1530: updU_gate_b (10), 1540: updU_cand_w (200)
// 1740 : updL_gate_w (200), 1940: updL_gate_b (10), 1950: updL_cand_w (200)

__global__ void __launch_bounds__(256, 2) k2_kernel(P27 p) {
    const float* g_xhu  = p.a[1];
    const float* g_xhl  = p.a[2];
    const float* g_xf   = p.a[3];
    const float* g_xp   = p.a[4];
    const float* w_pdp1 = p.a[5];
    const float* w_pdp2 = p.a[6];
    const float* w_att  = p.a[7];
    const float* b_att  = p.a[8];
    const float* w_cua  = p.a[9];
    const float* b_cua  = p.a[10];
    const float* w_cu   = p.a[11];
    const float* w_cla  = p.a[12];
    const float* b_cla  = p.a[13];
    const float* w_cl   = p.a[14];
    const float* b_dua  = p.a[16];
    const float* w_du   = p.a[17];
    const float* w_dua  = p.a[15];
    const float* w_dla  = p.a[18];
    const float* b_dla  = p.a[19];
    const float* w_dl   = p.a[20];
    const float* w_ugu  = p.a[21];
    const float* b_ugu  = p.a[22];
    const float* w_ucu  = p.a[23];
    const float* w_ugl  = p.a[24];
    const float* b_ugl  = p.a[25];
    const float* w_ucl  = p.a[26];
    float* out = p.out;

    __shared__ u64 s_small[2150];
    __shared__ u64 s_dpu[256 * 11];  // padded stride 11 -> conflict-light 64-bit access

    const int tid = threadIdx.x;
    {
        for (int i = tid; i < 400; i += 256) { int o = i / 20, k = i % 20; s_small[i] = dup2(w_pdp1[o * 276 + 256 + k]); }
        for (int i = tid; i < 200; i += 256) s_small[400 + i] = dup2(w_pdp2[i]);
        for (int i = tid; i < 22;  i += 256) s_small[600 + i] = (i < 20) ? dup2(w_att[i]) : dup2(b_att[i - 20]);
        for (int i = tid; i < 44;  i += 256) s_small[622 + i] = (i < 40) ? dup2(w_cua[i]) : dup2(b_cua[i - 40]);
        for (int i = tid; i < 200; i += 256) s_small[666 + i] = dup2(w_cu[i]);
        for (int i = tid; i < 22;  i += 256) s_small[866 + i] = (i < 20) ? dup2(w_cla[i]) : dup2(b_cla[i - 20]);
        for (int i = tid; i < 200; i += 256) s_small[888 + i] = dup2(w_cl[i]);
        for (int i = tid; i < 21;  i += 256) s_small[1088 + i] = (i < 20) ? dup2(w_dua[256 + i]) : dup2(b_dua[0]);
        for (int i = tid; i < 100; i += 256) s_small[1109 + i] = dup2(w_du[i]);
        for (int i = tid; i < 21;  i += 256) s_small[1209 + i] = (i < 20) ? dup2(w_dla[256 + i]) : dup2(b_dla[0]);
        for (int i = tid; i < 100; i += 256) s_small[1230 + i] = dup2(w_dl[i]);
        for (int i = tid; i < 210; i += 256) s_small[1330 + i] = (i < 200) ? dup2(w_ugu[i]) : dup2(b_ugu[i - 200]);
        for (int i = tid; i < 200; i += 256) s_small[1540 + i] = dup2(w_ucu[i]);
        for (int i = tid; i < 210; i += 256) s_small[1740 + i] = (i < 200) ? dup2(w_ugl[i]) : dup2(b_ugl[i - 200]);
        for (int i = tid; i < 200; i += 256) s_small[1950 + i] = dup2(w_ucl[i]);
    }
    __syncthreads();

    const int pair = blockIdx.x * 256 + tid;
    const int pix  = pair * 2;
    const int n    = pix >> 14;
    const int hw   = pix & (HWV - 1);
    const size_t vb = (size_t)n * HIDN * HWV + hw;
    const u64* hac = g_hacc + pair;

    u64 xu[10], xl[10];
#pragma unroll
    for (int i = 0; i < 10; i++) {
        xu[i] = *(const u64*)(g_xhu + vb + (size_t)i * HWV);
        xl[i] = *(const u64*)(g_xhl + vb + (size_t)i * HWV);
    }

    // ---- pdp: tt then dp; dpu stashed to smem ----
    u64 dpl[10];
    {
        u64 tt[20];
#pragma unroll
        for (int o = 0; o < 20; o++) {
            u64 a = hac[(size_t)o * NPAIR];
#pragma unroll
            for (int k = 0; k < 10; k++) a = ffma2(xu[k], s_small[o * 20 + k], a);
#pragma unroll
            for (int k = 0; k < 10; k++) a = ffma2(xl[k], s_small[o * 20 + 10 + k], a);
            tt[o] = relu2(a);
        }
#pragma unroll
        for (int o = 0; o < 10; o++) {
            u64 a = 0ULL, b = 0ULL;
#pragma unroll
            for (int i = 0; i < 10; i++) {
                a = ffma2(tt[i],      s_small[400 + o * 10 + i], a);
                b = ffma2(tt[10 + i], s_small[500 + o * 10 + i], b);
            }
            s_dpu[tid * 11 + o] = relu2(a);  // dpu stash
            dpl[o] = relu2(b);
        }
    }
    u64 agu, agl;
    {
        u64 a = s_small[620], b = s_small[621];
#pragma unroll
        for (int i = 0; i < 10; i++) {
            a = ffma2(xu[i], s_small[600 + i], a);
            b = ffma2(xl[i], s_small[610 + i], b);
        }
        agu = sigmoid2(a);
        agl = sigmoid2(b);
    }
    // xl is dead from here until the L half (reloaded there)

    u64 xfv[10];
#pragma unroll
    for (int i = 0; i < 10; i++) xfv[i] = *(const u64*)(g_xf + vb + (size_t)i * HWV);

    // ================= U half =================
    {
        u64 msg[10];
#pragma unroll
        for (int i = 0; i < 10; i++) msg[i] = 0ULL;
#pragma unroll
        for (int pp = 0; pp < 4; pp++) {
            u64 xv[10];
            const float* xpp = g_xp + ((size_t)(pp * NIMG + n) * HIDN) * HWV + hw;
#pragma unroll
            for (int i = 0; i < 10; i++) xv[i] = *(const u64*)(xpp + (size_t)i * HWV);
            u64 s = s_small[662 + pp];
#pragma unroll
            for (int i = 0; i < 10; i++) s = ffma2(xv[i], s_small[622 + pp * 10 + i], s);
            u64 ca = sigmoid2(s);
#pragma unroll
            for (int i = 0; i < 10; i++) msg[i] = ffma2(xv[i], ca, msg[i]);
        }
        u64 m[10];
#pragma unroll
        for (int o = 0; o < 10; o++) {
            u64 a = 0ULL;
#pragma unroll
            for (int i = 0; i < 10; i++) a = ffma2(xu[i],  s_small[666 + o * 20 + i], a);
#pragma unroll
            for (int i = 0; i < 10; i++) a = ffma2(msg[i], s_small[666 + o * 20 + 10 + i], a);
            m[o] = relu2(a);                  // xphu
            m[o] = ffma2(dpl[o], agl, m[o]);  // + dp_l*ag_l
            m[o] = ffma2(xu[o],  agu, m[o]);  // + xh_u*ag_u
        }
        u64 attu;
        {
            u64 s = fadd2(hac[(size_t)20 * NPAIR], s_small[1108]);
#pragma unroll
            for (int i = 0; i < 10; i++) s = ffma2(xfv[i], s_small[1088 + i], s);
#pragma unroll
            for (int i = 0; i < 10; i++) s = ffma2(xu[i],  s_small[1098 + i], s);
            attu = sigmoid2(s);
        }
        *(u64*)(out + OUT_ATTU + (size_t)n * HWV + hw) = attu;
        {
            u64 xfa[10];
#pragma unroll
            for (int i = 0; i < 10; i++) xfa[i] = fmul2(xfv[i], attu);
#pragma unroll
            for (int o = 0; o < 10; o++) {
                u64 a = 0ULL;
#pragma unroll
                for (int i = 0; i < 10; i++) a = ffma2(xfa[i], s_small[1109 + o * 10 + i], a);
                m[o] = fadd2(m[o], relu2(a)); // + xfhu
            }
        }
#pragma unroll
        for (int o = 0; o < 10; o++) {
            u64 g  = s_small[1530 + o];
            u64 cd = 0ULL;
#pragma unroll
            for (int i = 0; i < 10; i++) {
                g  = ffma2(xu[i], s_small[1330 + o * 20 + i], g);
                cd = ffma2(xu[i], s_small[1540 + o * 20 + i], cd);
            }
#pragma unroll
            for (int i = 0; i < 10; i++) {
                g  = ffma2(m[i], s_small[1330 + o * 20 + 10 + i], g);
                cd = ffma2(m[i], s_small[1540 + o * 20 + 10 + i], cd);
            }
            g  = sigmoid2(g);
            cd = relu2(cd);
            u64 res = ffma2(g, fadd2(cd, neg2(xu[o])), xu[o]);  // xu*(1-g)+cd*g
            *(u64*)(out + (size_t)(n * HIDN + o) * HWV + hw) = res;
        }
    }

    // ================= L half =================
    {
        // reload xl, xfv from gmem (cheap; keeps register peak low)
        u64 xlv[10], xf2[10];
#pragma unroll
        for (int i = 0; i < 10; i++) {
            xlv[i] = *(const u64*)(g_xhl + vb + (size_t)i * HWV);
            xf2[i] = *(const u64*)(g_xf  + vb + (size_t)i * HWV);
        }
        u64 msg[10];
#pragma unroll
        for (int i = 0; i < 10; i++) msg[i] = 0ULL;
#pragma unroll
        for (int pp = 0; pp < 2; pp++) {
            u64 xv[10];
            const float* xpp = g_xp + ((size_t)((4 + pp) * NIMG + n) * HIDN) * HWV + hw;
#pragma unroll
            for (int i = 0; i < 10; i++) xv[i] = *(const u64*)(xpp + (size_t)i * HWV);
            u64 s = s_small[886 + pp];
#pragma unroll
            for (int i = 0; i < 10; i++) s = ffma2(xv[i], s_small[866 + pp * 10 + i], s);
            u64 ca = sigmoid2(s);
#pragma unroll
            for (int i = 0; i < 10; i++) msg[i] = ffma2(xv[i], ca, msg[i]);
        }
        u64 m[10];
#pragma unroll
        for (int o = 0; o < 10; o++) {
            u64 a = 0ULL;
#pragma unroll
            for (int i = 0; i < 10; i++) a = ffma2(xlv[i], s_small[888 + o * 20 + i], a);
#pragma unroll
            for (int i = 0; i < 10; i++) a = ffma2(msg[i], s_small[888 + o * 20 + 10 + i], a);
            m[o] = relu2(a);                             // xphl
            m[o] = ffma2(s_dpu[tid * 11 + o], agu, m[o]); // + dp_u*ag_u
            m[o] = ffma2(xlv[o], agl, m[o]);              // + xh_l*ag_l
        }
        u64 attl;
        {
            u64 s = fadd2(hac[(size_t)21 * NPAIR], s_small[1229]);
#pragma unroll
            for (int i = 0; i < 10; i++) s = ffma2(xf2[i], s_small[1209 + i], s);
#pragma unroll
            for (int i = 0; i < 10; i++) s = ffma2(xlv[i], s_small[1219 + i], s);
            attl = sigmoid2(s);
        }
        *(u64*)(out + OUT_ATTL + (size_t)n * HWV + hw) = attl;
        {
            u64 xfa[10];
#pragma unroll
            for (int i = 0; i < 10; i++) xfa[i] = fmul2(xf2[i], attl);
#pragma unroll
            for (int o = 0; o < 10; o++) {
                u64 a = 0ULL;
#pragma unroll
                for (int i = 0; i < 10; i++) a = ffma2(xfa[i], s_small[1230 + o * 10 + i], a);
                m[o] = fadd2(m[o], relu2(a)); // + xfhl
            }
        }
#pragma unroll
        for (int o = 0; o < 10; o++) {
            u64 g  = s_small[1940 + o];
            u64 cd = 0ULL;
#pragma unroll
            for (int i = 0; i < 10; i++) {
                g  = ffma2(xlv[i], s_small[1740 + o * 20 + i], g);
                cd = ffma2(xlv[i], s_small[1950 + o * 20 + i], cd);
            }
#pragma unroll
            for (int i = 0; i < 10; i++) {
                g  = ffma2(m[i], s_small[1740 + o * 20 + 10 + i], g);
                cd = ffma2(m[i], s_small[1950 + o * 20 + 10 + i], cd);
            }
            g  = sigmoid2(g);
            cd = relu2(cd);
            u64 res = ffma2(g, fadd2(cd, neg2(xlv[o])), xlv[o]);
            *(u64*)(out + OUT_XHL + (size_t)(n * HIDN + o) * HWV + hw) = res;
        }
    }
}

extern "C" void kernel_launch(void* const* d_in, const int* in_sizes, int n_in,
                              void* d_out, int out_size) {
    k1_kernel<<<256, 256>>>((const float*)d_in[0], (const float*)d_in[5],
                            (const float*)d_in[15], (const float*)d_in[18]);
    P27 p;
    for (int i = 0; i < 27; i++) p.a[i] = (const float*)d_in[i];
    p.out = (float*)d_out;
    k2_kernel<<<256, 256>>>(p);
}

// round 5
// speedup vs baseline: 1.4673x; 1.4673x over previous
#include <cuda_runtime.h>

typedef unsigned long long u64;

#define HIDN 10
#define CCH  256
#define HWV  16384
#define NIMG 8
#define NPAIR 65536
// output offsets (floats)
#define OUT_XHL  1310720
#define OUT_ATTU 2621440
#define OUT_ATTL 2752512

// scratch: 22 planes of (pixA,pixB) packed dots, [22][NPAIR] u64 = 11.5 MiB
__device__ u64 g_hacc[22 * NPAIR];

// ---------- packed f32x2 helpers ----------
__device__ __forceinline__ u64 ffma2(u64 a, u64 b, u64 c) {
    u64 d; asm("fma.rn.f32x2 %0,%1,%2,%3;" : "=l"(d) : "l"(a), "l"(b), "l"(c)); return d;
}
__device__ __forceinline__ u64 fmul2(u64 a, u64 b) {
    u64 d; asm("mul.rn.f32x2 %0,%1,%2;" : "=l"(d) : "l"(a), "l"(b)); return d;
}
__device__ __forceinline__ u64 fadd2(u64 a, u64 b) {
    u64 d; asm("add.rn.f32x2 %0,%1,%2;" : "=l"(d) : "l"(a), "l"(b)); return d;
}
__device__ __forceinline__ u64 pack2(float x, float y) {
    u64 d; asm("mov.b64 %0,{%1,%2};" : "=l"(d) : "f"(x), "f"(y)); return d;
}
__device__ __forceinline__ void unpack2(u64 a, float& x, float& y) {
    asm("mov.b64 {%0,%1},%2;" : "=f"(x), "=f"(y) : "l"(a));
}
__device__ __forceinline__ u64 dup2(float x) { return pack2(x, x); }
__device__ __forceinline__ u64 relu2(u64 a) {
    float x, y; unpack2(a, x, y);
    return pack2(fmaxf(x, 0.f), fmaxf(y, 0.f));
}
__device__ __forceinline__ u64 sigmoid2(u64 a) {
    float x, y; unpack2(a, x, y);
    x = __fdividef(1.f, 1.f + __expf(-x));
    y = __fdividef(1.f, 1.f + __expf(-y));
    return pack2(x, y);
}
__device__ __forceinline__ u64 neg2(u64 a) { return a ^ 0x8000000080000000ULL; }

// 16B vector fetch of two dup'd weight u64s
struct uu2 { u64 x, y; };
__device__ __forceinline__ uu2 lds2(const u64* p) {
    uu2 r;
    asm("ld.shared.v2.u64 {%0,%1}, [%2];" : "=l"(r.x), "=l"(r.y) : "l"(__cvta_generic_to_shared(p)));
    return r;
}

// ============================================================================
// Kernel 1: 22 dots over 256 h_fea channels per pixel-pair.
// acc[j] = (dot_j(pixA), dot_j(pixB)); h loaded as float2 -> u64 used directly.
// Weights duplicated (w,w); fetched two-at-a-time with LDS.128.
// ============================================================================

__device__ __forceinline__ void k1comp(u64 (&acc)[22], const u64 (&hv)[8],
                                       const u64* swrow) {
#pragma unroll
    for (int u = 0; u < 8; u++) {
        u64 h2 = hv[u];
        const u64* wr = swrow + u * 22;
#pragma unroll
        for (int jp = 0; jp < 11; jp++) {
            uu2 w = lds2(wr + 2 * jp);
            acc[2 * jp]     = ffma2(h2, w.x, acc[2 * jp]);
            acc[2 * jp + 1] = ffma2(h2, w.y, acc[2 * jp + 1]);
        }
    }
}

__global__ void __launch_bounds__(256, 2) k1_kernel(const float* __restrict__ hfea,
                                                    const float* __restrict__ w_pdp1,
                                                    const float* __restrict__ w_dua,
                                                    const float* __restrict__ w_dla) {
    __shared__ __align__(16) u64 sw[256 * 22];   // 22 dup'd weights per channel (176B rows)
    const int tid = threadIdx.x;
    for (int i = tid; i < 256 * 22; i += 256) {
        int c = i / 22, j = i % 22;
        float w;
        if (j < 20)       w = w_pdp1[j * 276 + c];
        else if (j == 20) w = w_dua[c];
        else              w = w_dla[c];
        sw[i] = dup2(w);
    }
    __syncthreads();

    const int pair = blockIdx.x * 256 + tid;
    const int pix  = pair * 2;
    const int n    = pix >> 14;
    const int hw   = pix & (HWV - 1);
    const float* hp = hfea + (size_t)n * CCH * HWV + hw;

    u64 acc[22];
#pragma unroll
    for (int j = 0; j < 22; j++) acc[j] = 0ULL;

    u64 hv0[8], hv1[8];
#pragma unroll
    for (int u = 0; u < 8; u++) hv0[u] = *(const u64*)(hp + (size_t)u * HWV);
    const float* hq = hp + (size_t)8 * HWV;   // points at channel group c0+8

#pragma unroll 1
    for (int c0 = 0; c0 < 240; c0 += 16) {
#pragma unroll
        for (int u = 0; u < 8; u++) hv1[u] = *(const u64*)(hq + (size_t)u * HWV);
        k1comp(acc, hv0, sw + c0 * 22);
#pragma unroll
        for (int u = 0; u < 8; u++) hv0[u] = *(const u64*)(hq + (size_t)(8 + u) * HWV);
        k1comp(acc, hv1, sw + (c0 + 8) * 22);
        hq += (size_t)16 * HWV;
    }
    // tail: hv0 = ch 240-247, hq = ch 248
#pragma unroll
    for (int u = 0; u < 8; u++) hv1[u] = *(const u64*)(hq + (size_t)u * HWV);
    k1comp(acc, hv0, sw + 240 * 22);
    k1comp(acc, hv1, sw + 248 * 22);

    u64* gp = g_hacc + pair;
#pragma unroll
    for (int j = 0; j < 22; j++) gp[(size_t)j * NPAIR] = acc[j];
}

// ============================================================================
// Kernel 2: HID=10 graph ops, packed over the pixel pair.
// ============================================================================

struct P27 {
    const float* a[27];
    float* out;
};

#define K2T 128

// s_small offsets (u64 units), all values duplicated (w,w); all weight-row
// starts are EVEN so paired LDS.128 fetches are 16B-aligned.
// 0    : pdp_w1 tail [o*20+k] (400)
// 400  : pdp_w2 flat (200)
// 600  : att_w (20), 620: att_b (2)
// 622  : compU_att_w (40), 662: compU_att_b (4), 666: compU_w (200)
// 866  : compL_att_w (20), 886: compL_att_b (2), 888: compL_w (200)
// 1088 : decU_att tail (20), 1108: decU_att_b (1), [1109 pad], 1110: decU_w (100)
// 1210 : decL_att tail (20), 1230: decL_att_b (1), [1231 pad], 1232: decL_w (100)
// 1332 : updU_gate_w (200), 1532: updU_gate_b (10), 1542: updU_cand_w (200)
// 1742 : updL_gate_w (200), 1942: updL_gate_b (10), 1952: updL_cand_w (200)
// total 2152

__global__ void __launch_bounds__(K2T, 4) k2_kernel(P27 p) {
    const float* g_xhu  = p.a[1];
    const float* g_xhl  = p.a[2];
    const float* g_xf   = p.a[3];
    const float* g_xp   = p.a[4];
    const float* w_pdp1 = p.a[5];
    const float* w_pdp2 = p.a[6];
    const float* w_att  = p.a[7];
    const float* b_att  = p.a[8];
    const float* w_cua  = p.a[9];
    const float* b_cua  = p.a[10];
    const float* w_cu   = p.a[11];
    const float* w_cla  = p.a[12];
    const float* b_cla  = p.a[13];
    const float* w_cl   = p.a[14];
    const float* w_dua  = p.a[15];
    const float* b_dua  = p.a[16];
    const float* w_du   = p.a[17];
    const float* w_dla  = p.a[18];
    const float* b_dla  = p.a[19];
    const float* w_dl   = p.a[20];
    const float* w_ugu  = p.a[21];
    const float* b_ugu  = p.a[22];
    const float* w_ucu  = p.a[23];
    const float* w_ugl  = p.a[24];
    const float* b_ugl  = p.a[25];
    const float* w_ucl  = p.a[26];
    float* out = p.out;

    __shared__ __align__(16) u64 s_small[2152];
    __shared__ u64 s_dpu[K2T * 11];  // padded stride 11 -> conflict-light

    const int tid = threadIdx.x;
    {
        for (int i = tid; i < 400; i += K2T) { int o = i / 20, k = i % 20; s_small[i] = dup2(w_pdp1[o * 276 + 256 + k]); }
        for (int i = tid; i < 200; i += K2T) s_small[400 + i] = dup2(w_pdp2[i]);
        for (int i = tid; i < 22;  i += K2T) s_small[600 + i] = (i < 20) ? dup2(w_att[i]) : dup2(b_att[i - 20]);
        for (int i = tid; i < 44;  i += K2T) s_small[622 + i] = (i < 40) ? dup2(w_cua[i]) : dup2(b_cua[i - 40]);
        for (int i = tid; i < 200; i += K2T) s_small[666 + i] = dup2(w_cu[i]);
        for (int i = tid; i < 22;  i += K2T) s_small[866 + i] = (i < 20) ? dup2(w_cla[i]) : dup2(b_cla[i - 20]);
        for (int i = tid; i < 200; i += K2T) s_small[888 + i] = dup2(w_cl[i]);
        for (int i = tid; i < 21;  i += K2T) s_small[1088 + i] = (i < 20) ? dup2(w_dua[256 + i]) : dup2(b_dua[0]);
        for (int i = tid; i < 100; i += K2T) s_small[1110 + i] = dup2(w_du[i]);
        for (int i = tid; i < 21;  i += K2T) s_small[1210 + i] = (i < 20) ? dup2(w_dla[256 + i]) : dup2(b_dla[0]);
        for (int i = tid; i < 100; i += K2T) s_small[1232 + i] = dup2(w_dl[i]);
        for (int i = tid; i < 210; i += K2T) s_small[1332 + i] = (i < 200) ? dup2(w_ugu[i]) : dup2(b_ugu[i - 200]);
        for (int i = tid; i < 200; i += K2T) s_small[1542 + i] = dup2(w_ucu[i]);
        for (int i = tid; i < 210; i += K2T) s_small[1742 + i] = (i < 200) ? dup2(w_ugl[i]) : dup2(b_ugl[i - 200]);
        for (int i = tid; i < 200; i += K2T) s_small[1952 + i] = dup2(w_ucl[i]);
    }
    __syncthreads();

    const int pair = blockIdx.x * K2T + tid;
    const int pix  = pair * 2;
    const int n    = pix >> 14;
    const int hw   = pix & (HWV - 1);
    const size_t vb = (size_t)n * HIDN * HWV + hw;
    const u64* hac = g_hacc + pair;

    u64 xu[10], xl[10];
#pragma unroll
    for (int i = 0; i < 10; i++) {
        xu[i] = *(const u64*)(g_xhu + vb + (size_t)i * HWV);
        xl[i] = *(const u64*)(g_xhl + vb + (size_t)i * HWV);
    }

    // ---- pdp: tt then dp; dpu stashed to smem ----
    u64 dpl[10];
    {
        u64 tt[20];
#pragma unroll
        for (int o = 0; o < 20; o++) {
            u64 a = hac[(size_t)o * NPAIR];
            const u64* wr = s_small + o * 20;
#pragma unroll
            for (int k = 0; k < 10; k += 2) {
                uu2 w = lds2(wr + k);
                a = ffma2(xu[k], w.x, a);
                a = ffma2(xu[k + 1], w.y, a);
            }
#pragma unroll
            for (int k = 0; k < 10; k += 2) {
                uu2 w = lds2(wr + 10 + k);
                a = ffma2(xl[k], w.x, a);
                a = ffma2(xl[k + 1], w.y, a);
            }
            tt[o] = relu2(a);
        }
#pragma unroll
        for (int o = 0; o < 10; o++) {
            u64 a = 0ULL, b = 0ULL;
#pragma unroll
            for (int i = 0; i < 10; i += 2) {
                uu2 wa = lds2(s_small + 400 + o * 10 + i);
                uu2 wb = lds2(s_small + 500 + o * 10 + i);
                a = ffma2(tt[i],      wa.x, a);
                a = ffma2(tt[i + 1],  wa.y, a);
                b = ffma2(tt[10 + i], wb.x, b);
                b = ffma2(tt[11 + i], wb.y, b);
            }
            s_dpu[tid * 11 + o] = relu2(a);  // dpu stash
            dpl[o] = relu2(b);
        }
    }
    u64 agu, agl;
    {
        u64 a = s_small[620], b = s_small[621];
#pragma unroll
        for (int i = 0; i < 10; i += 2) {
            uu2 wa = lds2(s_small + 600 + i);
            uu2 wb = lds2(s_small + 610 + i);
            a = ffma2(xu[i], wa.x, a);
            a = ffma2(xu[i + 1], wa.y, a);
            b = ffma2(xl[i], wb.x, b);
            b = ffma2(xl[i + 1], wb.y, b);
        }
        agu = sigmoid2(a);
        agl = sigmoid2(b);
    }

    u64 xfv[10];
#pragma unroll
    for (int i = 0; i < 10; i++) xfv[i] = *(const u64*)(g_xf + vb + (size_t)i * HWV);

    // ================= U half =================
    {
        u64 msg[10];
#pragma unroll
        for (int i = 0; i < 10; i++) msg[i] = 0ULL;
#pragma unroll
        for (int pp = 0; pp < 4; pp++) {
            u64 xv[10];
            const float* xpp = g_xp + ((size_t)(pp * NIMG + n) * HIDN) * HWV + hw;
#pragma unroll
            for (int i = 0; i < 10; i++) xv[i] = *(const u64*)(xpp + (size_t)i * HWV);
            u64 s = s_small[662 + pp];
#pragma unroll
            for (int i = 0; i < 10; i += 2) {
                uu2 w = lds2(s_small + 622 + pp * 10 + i);
                s = ffma2(xv[i], w.x, s);
                s = ffma2(xv[i + 1], w.y, s);
            }
            u64 ca = sigmoid2(s);
#pragma unroll
            for (int i = 0; i < 10; i++) msg[i] = ffma2(xv[i], ca, msg[i]);
        }
        u64 m[10];
#pragma unroll
        for (int o = 0; o < 10; o++) {
            u64 a = 0ULL;
            const u64* wr = s_small + 666 + o * 20;
#pragma unroll
            for (int i = 0; i < 10; i += 2) {
                uu2 wa = lds2(wr + i);
                uu2 wb = lds2(wr + 10 + i);
                a = ffma2(xu[i],  wa.x, a);
                a = ffma2(xu[i + 1], wa.y, a);
                a = ffma2(msg[i], wb.x, a);
                a = ffma2(msg[i + 1], wb.y, a);
            }
            m[o] = relu2(a);                  // xphu
            m[o] = ffma2(dpl[o], agl, m[o]);  // + dp_l*ag_l
            m[o] = ffma2(xu[o],  agu, m[o]);  // + xh_u*ag_u
        }
        u64 attu;
        {
            u64 s = fadd2(hac[(size_t)20 * NPAIR], s_small[1108]);
#pragma unroll
            for (int i = 0; i < 10; i += 2) {
                uu2 wa = lds2(s_small + 1088 + i);
                uu2 wb = lds2(s_small + 1098 + i);
                s = ffma2(xfv[i], wa.x, s);
                s = ffma2(xfv[i + 1], wa.y, s);
                s = ffma2(xu[i],  wb.x, s);
                s = ffma2(xu[i + 1], wb.y, s);
            }
            attu = sigmoid2(s);
        }
        *(u64*)(out + OUT_ATTU + (size_t)n * HWV + hw) = attu;
        {
            u64 xfa[10];
#pragma unroll
            for (int i = 0; i < 10; i++) xfa[i] = fmul2(xfv[i], attu);
#pragma unroll
            for (int o = 0; o < 10; o++) {
                u64 a = 0ULL;
#pragma unroll
                for (int i = 0; i < 10; i += 2) {
                    uu2 w = lds2(s_small + 1110 + o * 10 + i);
                    a = ffma2(xfa[i], w.x, a);
                    a = ffma2(xfa[i + 1], w.y, a);
                }
                m[o] = fadd2(m[o], relu2(a)); // + xfhu
            }
        }
#pragma unroll
        for (int o = 0; o < 10; o++) {
            u64 g  = s_small[1532 + o];
            u64 cd = 0ULL;
            const u64* wg = s_small + 1332 + o * 20;
            const u64* wc = s_small + 1542 + o * 20;
#pragma unroll
            for (int i = 0; i < 10; i += 2) {
                uu2 a1 = lds2(wg + i);
                uu2 a2 = lds2(wc + i);
                g  = ffma2(xu[i], a1.x, g);
                g  = ffma2(xu[i + 1], a1.y, g);
                cd = ffma2(xu[i], a2.x, cd);
                cd = ffma2(xu[i + 1], a2.y, cd);
            }
#pragma unroll
            for (int i = 0; i < 10; i += 2) {
                uu2 a1 = lds2(wg + 10 + i);
                uu2 a2 = lds2(wc + 10 + i);
                g  = ffma2(m[i], a1.x, g);
                g  = ffma2(m[i + 1], a1.y, g);
                cd = ffma2(m[i], a2.x, cd);
                cd = ffma2(m[i + 1], a2.y, cd);
            }
            g  = sigmoid2(g);
            cd = relu2(cd);
            u64 res = ffma2(g, fadd2(cd, neg2(xu[o])), xu[o]);  // xu*(1-g)+cd*g
            *(u64*)(out + (size_t)(n * HIDN + o) * HWV + hw) = res;
        }
    }

    // ================= L half =================
    {
        u64 xlv[10], xf2[10];
#pragma unroll
        for (int i = 0; i < 10; i++) {
            xlv[i] = *(const u64*)(g_xhl + vb + (size_t)i * HWV);
            xf2[i] = *(const u64*)(g_xf  + vb + (size_t)i * HWV);
        }
        u64 msg[10];
#pragma unroll
        for (int i = 0; i < 10; i++) msg[i] = 0ULL;
#pragma unroll
        for (int pp = 0; pp < 2; pp++) {
            u64 xv[10];
            const float* xpp = g_xp + ((size_t)((4 + pp) * NIMG + n) * HIDN) * HWV + hw;
#pragma unroll
            for (int i = 0; i < 10; i++) xv[i] = *(const u64*)(xpp + (size_t)i * HWV);
            u64 s = s_small[886 + pp];
#pragma unroll
            for (int i = 0; i < 10; i += 2) {
                uu2 w = lds2(s_small + 866 + pp * 10 + i);
                s = ffma2(xv[i], w.x, s);
                s = ffma2(xv[i + 1], w.y, s);
            }
            u64 ca = sigmoid2(s);
#pragma unroll
            for (int i = 0; i < 10; i++) msg[i] = ffma2(xv[i], ca, msg[i]);
        }
        u64 m[10];
#pragma unroll
        for (int o = 0; o < 10; o++) {
            u64 a = 0ULL;
            const u64* wr = s_small + 888 + o * 20;
#pragma unroll
            for (int i = 0; i < 10; i += 2) {
                uu2 wa = lds2(wr + i);
                uu2 wb = lds2(wr + 10 + i);
                a = ffma2(xlv[i], wa.x, a);
                a = ffma2(xlv[i + 1], wa.y, a);
                a = ffma2(msg[i], wb.x, a);
                a = ffma2(msg[i + 1], wb.y, a);
            }
            m[o] = relu2(a);                              // xphl
            m[o] = ffma2(s_dpu[tid * 11 + o], agu, m[o]); // + dp_u*ag_u
            m[o] = ffma2(xlv[o], agl, m[o]);              // + xh_l*ag_l
        }
        u64 attl;
        {
            u64 s = fadd2(hac[(size_t)21 * NPAIR], s_small[1230]);
#pragma unroll
            for (int i = 0; i < 10; i += 2) {
                uu2 wa = lds2(s_small + 1210 + i);
                uu2 wb = lds2(s_small + 1220 + i);
                s = ffma2(xf2[i], wa.x, s);
                s = ffma2(xf2[i + 1], wa.y, s);
                s = ffma2(xlv[i], wb.x, s);
                s = ffma2(xlv[i + 1], wb.y, s);
            }
            attl = sigmoid2(s);
        }
        *(u64*)(out + OUT_ATTL + (size_t)n * HWV + hw) = attl;
        {
            u64 xfa[10];
#pragma unroll
            for (int i = 0; i < 10; i++) xfa[i] = fmul2(xf2[i], attl);
#pragma unroll
            for (int o = 0; o < 10; o++) {
                u64 a = 0ULL;
#pragma unroll
                for (int i = 0; i < 10; i += 2) {
                    uu2 w = lds2(s_small + 1232 + o * 10 + i);
                    a = ffma2(xfa[i], w.x, a);
                    a = ffma2(xfa[i + 1], w.y, a);
                }
                m[o] = fadd2(m[o], relu2(a)); // + xfhl
            }
        }
#pragma unroll
        for (int o = 0; o < 10; o++) {
            u64 g  = s_small[1942 + o];
            u64 cd = 0ULL;
            const u64* wg = s_small + 1742 + o * 20;
            const u64* wc = s_small + 1952 + o * 20;
#pragma unroll
            for (int i = 0; i < 10; i += 2) {
                uu2 a1 = lds2(wg + i);
                uu2 a2 = lds2(wc + i);
                g  = ffma2(xlv[i], a1.x, g);
                g  = ffma2(xlv[i + 1], a1.y, g);
                cd = ffma2(xlv[i], a2.x, cd);
                cd = ffma2(xlv[i + 1], a2.y, cd);
            }
#pragma unroll
            for (int i = 0; i < 10; i += 2) {
                uu2 a1 = lds2(wg + 10 + i);
                uu2 a2 = lds2(wc + 10 + i);
                g  = ffma2(m[i], a1.x, g);
                g  = ffma2(m[i + 1], a1.y, g);
                cd = ffma2(m[i], a2.x, cd);
                cd = ffma2(m[i + 1], a2.y, cd);
            }
            g  = sigmoid2(g);
            cd = relu2(cd);
            u64 res = ffma2(g, fadd2(cd, neg2(xlv[o])), xlv[o]);
            *(u64*)(out + OUT_XHL + (size_t)(n * HIDN + o) * HWV + hw) = res;
        }
    }
}

extern "C" void kernel_launch(void* const* d_in, const int* in_sizes, int n_in,
                              void* d_out, int out_size) {
    k1_kernel<<<256, 256>>>((const float*)d_in[0], (const float*)d_in[5],
                            (const float*)d_in[15], (const float*)d_in[18]);
    P27 p;
    for (int i = 0; i < 27; i++) p.a[i] = (const float*)d_in[i];
    p.out = (float*)d_out;
    k2_kernel<<<512, K2T>>>(p);
}

// round 9
// speedup vs baseline: 1.4997x; 1.0221x over previous
#include <cuda_runtime.h>

typedef unsigned long long u64;

#define HIDN 10
#define CCH  256
#define HWV  16384
#define NIMG 8
#define NPAIR 65536
// output offsets (floats)
#define OUT_XHL  1310720
#define OUT_ATTU 2621440
#define OUT_ATTL 2752512

// scratch: 22 planes of (pixA,pixB) packed dots, [22][NPAIR] u64 = 11.5 MiB
__device__ __align__(16) u64 g_hacc[22 * NPAIR];

// ---------- packed f32x2 helpers ----------
__device__ __forceinline__ u64 ffma2(u64 a, u64 b, u64 c) {
    u64 d; asm("fma.rn.f32x2 %0,%1,%2,%3;" : "=l"(d) : "l"(a), "l"(b), "l"(c)); return d;
}
__device__ __forceinline__ u64 fmul2(u64 a, u64 b) {
    u64 d; asm("mul.rn.f32x2 %0,%1,%2;" : "=l"(d) : "l"(a), "l"(b)); return d;
}
__device__ __forceinline__ u64 fadd2(u64 a, u64 b) {
    u64 d; asm("add.rn.f32x2 %0,%1,%2;" : "=l"(d) : "l"(a), "l"(b)); return d;
}
__device__ __forceinline__ u64 pack2(float x, float y) {
    u64 d; asm("mov.b64 %0,{%1,%2};" : "=l"(d) : "f"(x), "f"(y)); return d;
}
__device__ __forceinline__ void unpack2(u64 a, float& x, float& y) {
    asm("mov.b64 {%0,%1},%2;" : "=f"(x), "=f"(y) : "l"(a));
}
__device__ __forceinline__ u64 dup2(float x) { return pack2(x, x); }
__device__ __forceinline__ u64 relu2(u64 a) {
    float x, y; unpack2(a, x, y);
    return pack2(fmaxf(x, 0.f), fmaxf(y, 0.f));
}
__device__ __forceinline__ u64 sigmoid2(u64 a) {
    float x, y; unpack2(a, x, y);
    x = __fdividef(1.f, 1.f + __expf(-x));
    y = __fdividef(1.f, 1.f + __expf(-y));
    return pack2(x, y);
}
__device__ __forceinline__ u64 neg2(u64 a) { return a ^ 0x8000000080000000ULL; }

// 16B vector fetch of two dup'd weight u64s
struct uu2 { u64 x, y; };
__device__ __forceinline__ uu2 lds2(const u64* p) {
    uu2 r;
    asm("ld.shared.v2.u64 {%0,%1}, [%2];" : "=l"(r.x), "=l"(r.y) : "l"(__cvta_generic_to_shared(p)));
    return r;
}

// ============================================================================
// Kernel 1: 22 dots over 256 h_fea channels, 4 pixels (one quad) per thread.
// acc0[j] = (dot_j(px0), dot_j(px1)); acc1[j] = (dot_j(px2), dot_j(px3)).
// Per channel: 1 LDG.128 + 11 LDS.128 + 44 FFMA2.
// ============================================================================

__device__ __forceinline__ void k1comp(u64 (&acc0)[22], u64 (&acc1)[22],
                                       const ulonglong2 (&hv)[8], const u64* swrow) {
#pragma unroll
    for (int u = 0; u < 8; u++) {
        const u64 lo = hv[u].x;   // (px0, px1)
        const u64 hi = hv[u].y;   // (px2, px3)
        const u64* wr = swrow + u * 22;
#pragma unroll
        for (int jp = 0; jp < 11; jp++) {
            uu2 w = lds2(wr + 2 * jp);
            acc0[2 * jp]     = ffma2(lo, w.x, acc0[2 * jp]);
            acc0[2 * jp + 1] = ffma2(lo, w.y, acc0[2 * jp + 1]);
            acc1[2 * jp]     = ffma2(hi, w.x, acc1[2 * jp]);
            acc1[2 * jp + 1] = ffma2(hi, w.y, acc1[2 * jp + 1]);
        }
    }
}

__global__ void __launch_bounds__(256, 1) k1_kernel(const float* __restrict__ hfea,
                                                    const float* __restrict__ w_pdp1,
                                                    const float* __restrict__ w_dua,
                                                    const float* __restrict__ w_dla) {
    __shared__ __align__(16) u64 sw[256 * 22];   // 22 dup'd weights per channel (176B rows)
    const int tid = threadIdx.x;
    for (int i = tid; i < 256 * 22; i += 256) {
        int c = i / 22, j = i % 22;
        float w;
        if (j < 20)       w = w_pdp1[j * 276 + c];
        else if (j == 20) w = w_dua[c];
        else              w = w_dla[c];
        sw[i] = dup2(w);
    }
    __syncthreads();

    const int q   = blockIdx.x * 256 + tid;   // quad index, 32768 total
    const int pix = q * 4;
    const int n   = pix >> 14;
    const int hw  = pix & (HWV - 1);
    const float* hp = hfea + (size_t)n * CCH * HWV + hw;

    u64 acc0[22], acc1[22];
#pragma unroll
    for (int j = 0; j < 22; j++) { acc0[j] = 0ULL; acc1[j] = 0ULL; }

    ulonglong2 hv0[8], hv1[8];
#pragma unroll
    for (int u = 0; u < 8; u++) hv0[u] = *(const ulonglong2*)(hp + (size_t)u * HWV);
    const float* hq = hp + (size_t)8 * HWV;   // points at channel group c0+8

#pragma unroll 1
    for (int c0 = 0; c0 < 240; c0 += 16) {
#pragma unroll
        for (int u = 0; u < 8; u++) hv1[u] = *(const ulonglong2*)(hq + (size_t)u * HWV);
        k1comp(acc0, acc1, hv0, sw + c0 * 22);
#pragma unroll
        for (int u = 0; u < 8; u++) hv0[u] = *(const ulonglong2*)(hq + (size_t)(8 + u) * HWV);
        k1comp(acc0, acc1, hv1, sw + (c0 + 8) * 22);
        hq += (size_t)16 * HWV;
    }
    // tail: hv0 = ch 240-247, hq = ch 248
#pragma unroll
    for (int u = 0; u < 8; u++) hv1[u] = *(const ulonglong2*)(hq + (size_t)u * HWV);
    k1comp(acc0, acc1, hv0, sw + 240 * 22);
    k1comp(acc0, acc1, hv1, sw + 248 * 22);

    // store: pairs 2q (acc0) and 2q+1 (acc1) are contiguous -> STG.128
    u64* gp = g_hacc + 2 * q;
#pragma unroll
    for (int j = 0; j < 22; j++) {
        ulonglong2 v; v.x = acc0[j]; v.y = acc1[j];
        *(ulonglong2*)(gp + (size_t)j * NPAIR) = v;
    }
}

// ============================================================================
// Kernel 2: HID=10 graph ops, packed over the pixel pair.
// ============================================================================

struct P27 {
    const float* a[27];
    float* out;
};

#define K2T 128

// s_small offsets (u64 units), all values duplicated (w,w); all weight-row
// starts are EVEN so paired LDS.128 fetches are 16B-aligned.
// 0    : pdp_w1 tail [o*20+k] (400)
// 400  : pdp_w2 flat (200)
// 600  : att_w (20), 620: att_b (2)
// 622  : compU_att_w (40), 662: compU_att_b (4), 666: compU_w (200)
// 866  : compL_att_w (20), 886: compL_att_b (2), 888: compL_w (200)
// 1088 : decU_att tail (20), 1108: decU_att_b (1), [1109 pad], 1110: decU_w (100)
// 1210 : decL_att tail (20), 1230: decL_att_b (1), [1231 pad], 1232: decL_w (100)
// 1332 : updU_gate_w (200), 1532: updU_gate_b (10), 1542: updU_cand_w (200)
// 1742 : updL_gate_w (200), 1942: updL_gate_b (10), 1952: updL_cand_w (200)
// total 2152

__global__ void __launch_bounds__(K2T, 4) k2_kernel(P27 p) {
    const float* g_xhu  = p.a[1];
    const float* g_xhl  = p.a[2];
    const float* g_xf   = p.a[3];
    const float* g_xp   = p.a[4];
    const float* w_pdp1 = p.a[5];
    const float* w_pdp2 = p.a[6];
    const float* w_att  = p.a[7];
    const float* b_att  = p.a[8];
    const float* w_cua  = p.a[9];
    const float* b_cua  = p.a[10];
    const float* w_cu   = p.a[11];
    const float* w_cla  = p.a[12];
    const float* b_cla  = p.a[13];
    const float* w_cl   = p.a[14];
    const float* w_dua  = p.a[15];
    const float* b_dua  = p.a[16];
    const float* w_du   = p.a[17];
    const float* w_dla  = p.a[18];
    const float* b_dla  = p.a[19];
    const float* w_dl   = p.a[20];
    const float* w_ugu  = p.a[21];
    const float* b_ugu  = p.a[22];
    const float* w_ucu  = p.a[23];
    const float* w_ugl  = p.a[24];
    const float* b_ugl  = p.a[25];
    const float* w_ucl  = p.a[26];
    float* out = p.out;

    __shared__ __align__(16) u64 s_small[2152];
    __shared__ u64 s_dpu[K2T * 11];  // padded stride 11 -> conflict-light

    const int tid = threadIdx.x;
    {
        for (int i = tid; i < 400; i += K2T) { int o = i / 20, k = i % 20; s_small[i] = dup2(w_pdp1[o * 276 + 256 + k]); }
        for (int i = tid; i < 200; i += K2T) s_small[400 + i] = dup2(w_pdp2[i]);
        for (int i = tid; i < 22;  i += K2T) s_small[600 + i] = (i < 20) ? dup2(w_att[i]) : dup2(b_att[i - 20]);
        for (int i = tid; i < 44;  i += K2T) s_small[622 + i] = (i < 40) ? dup2(w_cua[i]) : dup2(b_cua[i - 40]);
        for (int i = tid; i < 200; i += K2T) s_small[666 + i] = dup2(w_cu[i]);
        for (int i = tid; i < 22;  i += K2T) s_small[866 + i] = (i < 20) ? dup2(w_cla[i]) : dup2(b_cla[i - 20]);
        for (int i = tid; i < 200; i += K2T) s_small[888 + i] = dup2(w_cl[i]);
        for (int i = tid; i < 21;  i += K2T) s_small[1088 + i] = (i < 20) ? dup2(w_dua[256 + i]) : dup2(b_dua[0]);
        for (int i = tid; i < 100; i += K2T) s_small[1110 + i] = dup2(w_du[i]);
        for (int i = tid; i < 21;  i += K2T) s_small[1210 + i] = (i < 20) ? dup2(w_dla[256 + i]) : dup2(b_dla[0]);
        for (int i = tid; i < 100; i += K2T) s_small[1232 + i] = dup2(w_dl[i]);
        for (int i = tid; i < 210; i += K2T) s_small[1332 + i] = (i < 200) ? dup2(w_ugu[i]) : dup2(b_ugu[i - 200]);
        for (int i = tid; i < 200; i += K2T) s_small[1542 + i] = dup2(w_ucu[i]);
        for (int i = tid; i < 210; i += K2T) s_small[1742 + i] = (i < 200) ? dup2(w_ugl[i]) : dup2(b_ugl[i - 200]);
        for (int i = tid; i < 200; i += K2T) s_small[1952 + i] = dup2(w_ucl[i]);
    }
    __syncthreads();

    const int pair = blockIdx.x * K2T + tid;
    const int pix  = pair * 2;
    const int n    = pix >> 14;
    const int hw   = pix & (HWV - 1);
    const size_t vb = (size_t)n * HIDN * HWV + hw;
    const u64* hac = g_hacc + pair;

    u64 xu[10], xl[10];
#pragma unroll
    for (int i = 0; i < 10; i++) {
        xu[i] = *(const u64*)(g_xhu + vb + (size_t)i * HWV);
        xl[i] = *(const u64*)(g_xhl + vb + (size_t)i * HWV);
    }

    // ---- pdp: tt then dp; dpu stashed to smem ----
    u64 dpl[10];
    {
        u64 tt[20];
#pragma unroll
        for (int o = 0; o < 20; o++) {
            u64 a = hac[(size_t)o * NPAIR];
            const u64* wr = s_small + o * 20;
#pragma unroll
            for (int k = 0; k < 10; k += 2) {
                uu2 w = lds2(wr + k);
                a = ffma2(xu[k], w.x, a);
                a = ffma2(xu[k + 1], w.y, a);
            }
#pragma unroll
            for (int k = 0; k < 10; k += 2) {
                uu2 w = lds2(wr + 10 + k);
                a = ffma2(xl[k], w.x, a);
                a = ffma2(xl[k + 1], w.y, a);
            }
            tt[o] = relu2(a);
        }
#pragma unroll
        for (int o = 0; o < 10; o++) {
            u64 a = 0ULL, b = 0ULL;
#pragma unroll
            for (int i = 0; i < 10; i += 2) {
                uu2 wa = lds2(s_small + 400 + o * 10 + i);
                uu2 wb = lds2(s_small + 500 + o * 10 + i);
                a = ffma2(tt[i],      wa.x, a);
                a = ffma2(tt[i + 1],  wa.y, a);
                b = ffma2(tt[10 + i], wb.x, b);
                b = ffma2(tt[11 + i], wb.y, b);
            }
            s_dpu[tid * 11 + o] = relu2(a);  // dpu stash
            dpl[o] = relu2(b);
        }
    }
    u64 agu, agl;
    {
        u64 a = s_small[620], b = s_small[621];
#pragma unroll
        for (int i = 0; i < 10; i += 2) {
            uu2 wa = lds2(s_small + 600 + i);
            uu2 wb = lds2(s_small + 610 + i);
            a = ffma2(xu[i], wa.x, a);
            a = ffma2(xu[i + 1], wa.y, a);
            b = ffma2(xl[i], wb.x, b);
            b = ffma2(xl[i + 1], wb.y, b);
        }
        agu = sigmoid2(a);
        agl = sigmoid2(b);
    }

    u64 xfv[10];
#pragma unroll
    for (int i = 0; i < 10; i++) xfv[i] = *(const u64*)(g_xf + vb + (size_t)i * HWV);

    // ================= U half =================
    {
        u64 msg[10];
#pragma unroll
        for (int i = 0; i < 10; i++) msg[i] = 0ULL;
#pragma unroll
        for (int pp = 0; pp < 4; pp++) {
            u64 xv[10];
            const float* xpp = g_xp + ((size_t)(pp * NIMG + n) * HIDN) * HWV + hw;
#pragma unroll
            for (int i = 0; i < 10; i++) xv[i] = *(const u64*)(xpp + (size_t)i * HWV);
            u64 s = s_small[662 + pp];
#pragma unroll
            for (int i = 0; i < 10; i += 2) {
                uu2 w = lds2(s_small + 622 + pp * 10 + i);
                s = ffma2(xv[i], w.x, s);
                s = ffma2(xv[i + 1], w.y, s);
            }
            u64 ca = sigmoid2(s);
#pragma unroll
            for (int i = 0; i < 10; i++) msg[i] = ffma2(xv[i], ca, msg[i]);
        }
        u64 m[10];
#pragma unroll
        for (int o = 0; o < 10; o++) {
            u64 a = 0ULL;
            const u64* wr = s_small + 666 + o * 20;
#pragma unroll
            for (int i = 0; i < 10; i += 2) {
                uu2 wa = lds2(wr + i);
                uu2 wb = lds2(wr + 10 + i);
                a = ffma2(xu[i],  wa.x, a);
                a = ffma2(xu[i + 1], wa.y, a);
                a = ffma2(msg[i], wb.x, a);
                a = ffma2(msg[i + 1], wb.y, a);
            }
            m[o] = relu2(a);                  // xphu
            m[o] = ffma2(dpl[o], agl, m[o]);  // + dp_l*ag_l
            m[o] = ffma2(xu[o],  agu, m[o]);  // + xh_u*ag_u
        }
        u64 attu;
        {
            u64 s = fadd2(hac[(size_t)20 * NPAIR], s_small[1108]);
#pragma unroll
            for (int i = 0; i < 10; i += 2) {
                uu2 wa = lds2(s_small + 1088 + i);
                uu2 wb = lds2(s_small + 1098 + i);
                s = ffma2(xfv[i], wa.x, s);
                s = ffma2(xfv[i + 1], wa.y, s);
                s = ffma2(xu[i],  wb.x, s);
                s = ffma2(xu[i + 1], wb.y, s);
            }
            attu = sigmoid2(s);
        }
        *(u64*)(out + OUT_ATTU + (size_t)n * HWV + hw) = attu;
        {
            u64 xfa[10];
#pragma unroll
            for (int i = 0; i < 10; i++) xfa[i] = fmul2(xfv[i], attu);
#pragma unroll
            for (int o = 0; o < 10; o++) {
                u64 a = 0ULL;
#pragma unroll
                for (int i = 0; i < 10; i += 2) {
                    uu2 w = lds2(s_small + 1110 + o * 10 + i);
                    a = ffma2(xfa[i], w.x, a);
                    a = ffma2(xfa[i + 1], w.y, a);
                }
                m[o] = fadd2(m[o], relu2(a)); // + xfhu
            }
        }
#pragma unroll
        for (int o = 0; o < 10; o++) {
            u64 g  = s_small[1532 + o];
            u64 cd = 0ULL;
            const u64* wg = s_small + 1332 + o * 20;
            const u64* wc = s_small + 1542 + o * 20;
#pragma unroll
            for (int i = 0; i < 10; i += 2) {
                uu2 a1 = lds2(wg + i);
                uu2 a2 = lds2(wc + i);
                g  = ffma2(xu[i], a1.x, g);
                g  = ffma2(xu[i + 1], a1.y, g);
                cd = ffma2(xu[i], a2.x, cd);
                cd = ffma2(xu[i + 1], a2.y, cd);
            }
#pragma unroll
            for (int i = 0; i < 10; i += 2) {
                uu2 a1 = lds2(wg + 10 + i);
                uu2 a2 = lds2(wc + 10 + i);
                g  = ffma2(m[i], a1.x, g);
                g  = ffma2(m[i + 1], a1.y, g);
                cd = ffma2(m[i], a2.x, cd);
                cd = ffma2(m[i + 1], a2.y, cd);
            }
            g  = sigmoid2(g);
            cd = relu2(cd);
            u64 res = ffma2(g, fadd2(cd, neg2(xu[o])), xu[o]);  // xu*(1-g)+cd*g
            *(u64*)(out + (size_t)(n * HIDN + o) * HWV + hw) = res;
        }
    }

    // ================= L half =================
    {
        u64 xlv[10], xf2[10];
#pragma unroll
        for (int i = 0; i < 10; i++) {
            xlv[i] = *(const u64*)(g_xhl + vb + (size_t)i * HWV);
            xf2[i] = *(const u64*)(g_xf  + vb + (size_t)i * HWV);
        }
        u64 msg[10];
#pragma unroll
        for (int i = 0; i < 10; i++) msg[i] = 0ULL;
#pragma unroll
        for (int pp = 0; pp < 2; pp++) {
            u64 xv[10];
            const float* xpp = g_xp + ((size_t)((4 + pp) * NIMG + n) * HIDN) * HWV + hw;
#pragma unroll
            for (int i = 0; i < 10; i++) xv[i] = *(const u64*)(xpp + (size_t)i * HWV);
            u64 s = s_small[886 + pp];
#pragma unroll
            for (int i = 0; i < 10; i += 2) {
                uu2 w = lds2(s_small + 866 + pp * 10 + i);
                s = ffma2(xv[i], w.x, s);
                s = ffma2(xv[i + 1], w.y, s);
            }
            u64 ca = sigmoid2(s);
#pragma unroll
            for (int i = 0; i < 10; i++) msg[i] = ffma2(xv[i], ca, msg[i]);
        }
        u64 m[10];
#pragma unroll
        for (int o = 0; o < 10; o++) {
            u64 a = 0ULL;
            const u64* wr = s_small + 888 + o * 20;
#pragma unroll
            for (int i = 0; i < 10; i += 2) {
                uu2 wa = lds2(wr + i);
                uu2 wb = lds2(wr + 10 + i);
                a = ffma2(xlv[i], wa.x, a);
                a = ffma2(xlv[i + 1], wa.y, a);
                a = ffma2(msg[i], wb.x, a);
                a = ffma2(msg[i + 1], wb.y, a);
            }
            m[o] = relu2(a);                              // xphl
            m[o] = ffma2(s_dpu[tid * 11 + o], agu, m[o]); // + dp_u*ag_u
            m[o] = ffma2(xlv[o], agl, m[o]);              // + xh_l*ag_l
        }
        u64 attl;
        {
            u64 s = fadd2(hac[(size_t)21 * NPAIR], s_small[1230]);
#pragma unroll
            for (int i = 0; i < 10; i += 2) {
                uu2 wa = lds2(s_small + 1210 + i);
                uu2 wb = lds2(s_small + 1220 + i);
                s = ffma2(xf2[i], wa.x, s);
                s = ffma2(xf2[i + 1], wa.y, s);
                s = ffma2(xlv[i], wb.x, s);
                s = ffma2(xlv[i + 1], wb.y, s);
            }
            attl = sigmoid2(s);
        }
        *(u64*)(out + OUT_ATTL + (size_t)n * HWV + hw) = attl;
        {
            u64 xfa[10];
#pragma unroll
            for (int i = 0; i < 10; i++) xfa[i] = fmul2(xf2[i], attl);
#pragma unroll
            for (int o = 0; o < 10; o++) {
                u64 a = 0ULL;
#pragma unroll
                for (int i = 0; i < 10; i += 2) {
                    uu2 w = lds2(s_small + 1232 + o * 10 + i);
                    a = ffma2(xfa[i], w.x, a);
                    a = ffma2(xfa[i + 1], w.y, a);
                }
                m[o] = fadd2(m[o], relu2(a)); // + xfhl
            }
        }
#pragma unroll
        for (int o = 0; o < 10; o++) {
            u64 g  = s_small[1942 + o];
            u64 cd = 0ULL;
            const u64* wg = s_small + 1742 + o * 20;
            const u64* wc = s_small + 1952 + o * 20;
#pragma unroll
            for (int i = 0; i < 10; i += 2) {
                uu2 a1 = lds2(wg + i);
                uu2 a2 = lds2(wc + i);
                g  = ffma2(xlv[i], a1.x, g);
                g  = ffma2(xlv[i + 1], a1.y, g);
                cd = ffma2(xlv[i], a2.x, cd);
                cd = ffma2(xlv[i + 1], a2.y, cd);
            }
#pragma unroll
            for (int i = 0; i < 10; i += 2) {
                uu2 a1 = lds2(wg + 10 + i);
                uu2 a2 = lds2(wc + 10 + i);
                g  = ffma2(m[i], a1.x, g);
                g  = ffma2(m[i + 1], a1.y, g);
                cd = ffma2(m[i], a2.x, cd);
                cd = ffma2(m[i + 1], a2.y, cd);
            }
            g  = sigmoid2(g);
            cd = relu2(cd);
            u64 res = ffma2(g, fadd2(cd, neg2(xlv[o])), xlv[o]);
            *(u64*)(out + OUT_XHL + (size_t)(n * HIDN + o) * HWV + hw) = res;
        }
    }
}

extern "C" void kernel_launch(void* const* d_in, const int* in_sizes, int n_in,
                              void* d_out, int out_size) {
    k1_kernel<<<128, 256>>>((const float*)d_in[0], (const float*)d_in[5],
                            (const float*)d_in[15], (const float*)d_in[18]);
    P27 p;
    for (int i = 0; i < 27; i++) p.a[i] = (const float*)d_in[i];
    p.out = (float*)d_out;
    k2_kernel<<<512, K2T>>>(p);
}

// round 10
// speedup vs baseline: 1.6988x; 1.1328x over previous
#include <cuda_runtime.h>

typedef unsigned long long u64;
typedef unsigned int u32;

#define HIDN 10
#define CCH  256
#define HWV  16384
#define NIMG 8
#define NPAIR 65536
#define NPIX 131072
// output offsets (floats)
#define OUT_XHL  1310720
#define OUT_ATTU 2621440
#define OUT_ATTL 2752512

// scratch: 22 planes of packed dots; float view [22][131072]
__device__ __align__(16) u64 g_hacc[22 * NPAIR];

// ---------- packed f32x2 helpers (k2) ----------
__device__ __forceinline__ u64 ffma2(u64 a, u64 b, u64 c) {
    u64 d; asm("fma.rn.f32x2 %0,%1,%2,%3;" : "=l"(d) : "l"(a), "l"(b), "l"(c)); return d;
}
__device__ __forceinline__ u64 fmul2(u64 a, u64 b) {
    u64 d; asm("mul.rn.f32x2 %0,%1,%2;" : "=l"(d) : "l"(a), "l"(b)); return d;
}
__device__ __forceinline__ u64 fadd2(u64 a, u64 b) {
    u64 d; asm("add.rn.f32x2 %0,%1,%2;" : "=l"(d) : "l"(a), "l"(b)); return d;
}
__device__ __forceinline__ u64 pack2(float x, float y) {
    u64 d; asm("mov.b64 %0,{%1,%2};" : "=l"(d) : "f"(x), "f"(y)); return d;
}
__device__ __forceinline__ void unpack2(u64 a, float& x, float& y) {
    asm("mov.b64 {%0,%1},%2;" : "=f"(x), "=f"(y) : "l"(a));
}
__device__ __forceinline__ u64 dup2(float x) { return pack2(x, x); }
__device__ __forceinline__ u64 relu2(u64 a) {
    float x, y; unpack2(a, x, y);
    return pack2(fmaxf(x, 0.f), fmaxf(y, 0.f));
}
__device__ __forceinline__ u64 sigmoid2(u64 a) {
    float x, y; unpack2(a, x, y);
    x = __fdividef(1.f, 1.f + __expf(-x));
    y = __fdividef(1.f, 1.f + __expf(-y));
    return pack2(x, y);
}
__device__ __forceinline__ u64 neg2(u64 a) { return a ^ 0x8000000080000000ULL; }

struct uu2 { u64 x, y; };
__device__ __forceinline__ uu2 lds2(const u64* p) {
    uu2 r;
    asm("ld.shared.v2.u64 {%0,%1}, [%2];" : "=l"(r.x), "=l"(r.y) : "l"(__cvta_generic_to_shared(p)));
    return r;
}

// ---------- tf32 / mma helpers (k1) ----------
__device__ __forceinline__ u32 tf32of(float f) {
    u32 u; asm("cvt.rna.tf32.f32 %0,%1;" : "=r"(u) : "f"(f)); return u;
}
__device__ __forceinline__ void mma_tf32(float (&d)[4], const u32 (&a)[4], const u32* b) {
    asm volatile(
        "mma.sync.aligned.m16n8k8.row.col.f32.tf32.tf32.f32 "
        "{%0,%1,%2,%3},{%4,%5,%6,%7},{%8,%9},{%0,%1,%2,%3};"
        : "+f"(d[0]), "+f"(d[1]), "+f"(d[2]), "+f"(d[3])
        : "r"(a[0]), "r"(a[1]), "r"(a[2]), "r"(a[3]), "r"(b[0]), "r"(b[1]));
}
__device__ __forceinline__ void cp16(float* dst, const float* src) {
    u32 ds = (u32)__cvta_generic_to_shared(dst);
    asm volatile("cp.async.cg.shared.global [%0], [%1], 16;" :: "r"(ds), "l"(src));
}
#define CP_COMMIT() asm volatile("cp.async.commit_group;" ::: "memory")
#define CP_WAIT1()  asm volatile("cp.async.wait_group 1;" ::: "memory")

// ============================================================================
// Kernel 1 (tensor): hacc[22][pix] = W[22x256] . hfea[256][pix]
// 3xTF32 split for fp32-class accuracy. Persistent 128 blocks, 256-px chunks.
// ============================================================================

#define HROW 264                      // smem row stride (floats): 16B aligned, conflict-free
#define HBUF (32 * HROW)              // one 32-channel tile
#define K1_SMEM_BYTES ((16384 + 2 * HBUF) * 4)

__global__ void __launch_bounds__(256) k1t_kernel(const float* __restrict__ hfea,
                                                  const float* __restrict__ w_pdp1,
                                                  const float* __restrict__ w_dua,
                                                  const float* __restrict__ w_dla) {
    extern __shared__ u32 smemu[];
    u32*   Whi  = smemu;              // [2 mtile][32 kstep][32 lane][4] = 8192
    u32*   Wlo  = smemu + 8192;       // 8192
    float* hbuf = (float*)(smemu + 16384);  // 2 x HBUF floats

    const int tid = threadIdx.x;
    const int w   = tid >> 5;
    const int l   = tid & 31;

    // ---- weight prep: split hi/lo, pre-swizzled into fragment order ----
    for (int s = tid; s < 2048; s += 256) {
        int t = s >> 10, rem = s & 1023, ks = rem >> 5, ln = rem & 31;
#pragma unroll
        for (int r = 0; r < 4; r++) {
            int row = 16 * t + (ln >> 2) + 8 * (r & 1);
            int col = 8 * ks + (ln & 3) + 4 * (r >> 1);
            float v = 0.f;
            if (row < 20)       v = w_pdp1[row * 276 + col];
            else if (row == 20) v = w_dua[col];
            else if (row == 21) v = w_dla[col];
            u32 hb = tf32of(v);
            float lf = v - __uint_as_float(hb);
            Whi[s * 4 + r] = hb;
            Wlo[s * 4 + r] = tf32of(lf);
        }
    }
    __syncthreads();

    const int bid = blockIdx.x;       // 0..127; chunks c = bid + 128*i, i<4

    // load cursor
    int lc = 0, lk = 0;
    // issue first load into buf 0
    {
        int c = bid;                  // lc==0
        int n = c >> 6, hw0 = (c & 63) << 8;
        const float* src0 = hfea + ((size_t)(n * CCH + 0 * 32) + 0) * HWV + hw0;
        int row = tid >> 3, seg0 = tid & 7;
        const float* srcr = src0 + (size_t)row * HWV;
        float* dstr = hbuf + row * HROW;
#pragma unroll
        for (int j = 0; j < 8; j++) { int seg = seg0 + j * 8; cp16(dstr + seg * 4, srcr + seg * 4); }
        lk = 1;
    }
    CP_COMMIT();

    int cb = 0;  // compute buffer
#pragma unroll 1
    for (int ci = 0; ci < 4; ci++) {
        const int c  = bid + ci * 128;
        const int n  = c >> 6;
        const int hw0 = (c & 63) << 8;

        float Cf[2][4][4];
#pragma unroll
        for (int t = 0; t < 2; t++)
#pragma unroll
            for (int nt = 0; nt < 4; nt++)
#pragma unroll
                for (int r = 0; r < 4; r++) Cf[t][nt][r] = 0.f;

#pragma unroll 1
        for (int kc = 0; kc < 8; kc++) {
            // issue next load into the other buffer
            if (lc < 4) {
                int c2 = bid + lc * 128;
                int n2 = c2 >> 6, hw2 = (c2 & 63) << 8;
                const float* src0 = hfea + ((size_t)(n2 * CCH + lk * 32)) * HWV + hw2;
                int row = tid >> 3, seg0 = tid & 7;
                const float* srcr = src0 + (size_t)row * HWV;
                float* dstr = hbuf + (cb ^ 1) * HBUF + row * HROW;
#pragma unroll
                for (int j = 0; j < 8; j++) { int seg = seg0 + j * 8; cp16(dstr + seg * 4, srcr + seg * 4); }
                if (++lk == 8) { lk = 0; lc++; }
            }
            CP_COMMIT();
            CP_WAIT1();
            __syncthreads();

            const float* hb = hbuf + cb * HBUF;
#pragma unroll
            for (int ks = 0; ks < 4; ks++) {
                const int gks = kc * 4 + ks;
                // A fragments (1 LDS.128 each)
                u32 ahi[2][4], alo[2][4];
#pragma unroll
                for (int t = 0; t < 2; t++) {
                    uint4 h4 = *(const uint4*)(Whi + ((t * 32 + gks) * 32 + l) * 4);
                    uint4 l4 = *(const uint4*)(Wlo + ((t * 32 + gks) * 32 + l) * 4);
                    ahi[t][0] = h4.x; ahi[t][1] = h4.y; ahi[t][2] = h4.z; ahi[t][3] = h4.w;
                    alo[t][0] = l4.x; alo[t][1] = l4.y; alo[t][2] = l4.z; alo[t][3] = l4.w;
                }
                // B fragments: b[k=(l&3)(+4)][n=l>>2]
                u32 bhi[4][2], blo[4][2];
                const int r0 = (8 * ks + (l & 3)) * HROW;
#pragma unroll
                for (int nt = 0; nt < 4; nt++) {
                    const int pxl = w * 32 + nt * 8 + (l >> 2);
                    float v0 = hb[r0 + pxl];
                    float v1 = hb[r0 + 4 * HROW + pxl];
                    u32 h0 = tf32of(v0), h1 = tf32of(v1);
                    bhi[nt][0] = h0; bhi[nt][1] = h1;
                    blo[nt][0] = tf32of(v0 - __uint_as_float(h0));
                    blo[nt][1] = tf32of(v1 - __uint_as_float(h1));
                }
#pragma unroll
                for (int t = 0; t < 2; t++)
#pragma unroll
                    for (int nt = 0; nt < 4; nt++) {
                        mma_tf32(Cf[t][nt], ahi[t], bhi[nt]);
                        mma_tf32(Cf[t][nt], ahi[t], blo[nt]);
                        mma_tf32(Cf[t][nt], alo[t], bhi[nt]);
                    }
            }
            __syncthreads();
            cb ^= 1;
        }

        // ---- store: rows 0..21, float2 per lane ----
        float* ob = (float*)g_hacc;
        const int lr  = l >> 2;
        const int pxo = 2 * (l & 3);
        const size_t pbase = (size_t)n * HWV + hw0;
#pragma unroll
        for (int t = 0; t < 2; t++)
#pragma unroll
            for (int nt = 0; nt < 4; nt++) {
                const int px = w * 32 + nt * 8 + pxo;
                const int row0 = 16 * t + lr;
                if (row0 < 22) {
                    float2 v; v.x = Cf[t][nt][0]; v.y = Cf[t][nt][1];
                    *(float2*)(ob + (size_t)row0 * NPIX + pbase + px) = v;
                }
                const int row1 = 16 * t + lr + 8;
                if (row1 < 22) {
                    float2 v; v.x = Cf[t][nt][2]; v.y = Cf[t][nt][3];
                    *(float2*)(ob + (size_t)row1 * NPIX + pbase + px) = v;
                }
            }
    }
}

// ============================================================================
// Kernel 2: HID=10 graph ops, packed over the pixel pair. (unchanged)
// ============================================================================

struct P27 {
    const float* a[27];
    float* out;
};

#define K2T 128

__global__ void __launch_bounds__(K2T, 4) k2_kernel(P27 p) {
    const float* g_xhu  = p.a[1];
    const float* g_xhl  = p.a[2];
    const float* g_xf   = p.a[3];
    const float* g_xp   = p.a[4];
    const float* w_pdp1 = p.a[5];
    const float* w_pdp2 = p.a[6];
    const float* w_att  = p.a[7];
    const float* b_att  = p.a[8];
    const float* w_cua  = p.a[9];
    const float* b_cua  = p.a[10];
    const float* w_cu   = p.a[11];
    const float* w_cla  = p.a[12];
    const float* b_cla  = p.a[13];
    const float* w_cl   = p.a[14];
    const float* w_dua  = p.a[15];
    const float* b_dua  = p.a[16];
    const float* w_du   = p.a[17];
    const float* w_dla  = p.a[18];
    const float* b_dla  = p.a[19];
    const float* w_dl   = p.a[20];
    const float* w_ugu  = p.a[21];
    const float* b_ugu  = p.a[22];
    const float* w_ucu  = p.a[23];
    const float* w_ugl  = p.a[24];
    const float* b_ugl  = p.a[25];
    const float* w_ucl  = p.a[26];
    float* out = p.out;

    __shared__ __align__(16) u64 s_small[2152];
    __shared__ u64 s_dpu[K2T * 11];

    const int tid = threadIdx.x;
    {
        for (int i = tid; i < 400; i += K2T) { int o = i / 20, k = i % 20; s_small[i] = dup2(w_pdp1[o * 276 + 256 + k]); }
        for (int i = tid; i < 200; i += K2T) s_small[400 + i] = dup2(w_pdp2[i]);
        for (int i = tid; i < 22;  i += K2T) s_small[600 + i] = (i < 20) ? dup2(w_att[i]) : dup2(b_att[i - 20]);
        for (int i = tid; i < 44;  i += K2T) s_small[622 + i] = (i < 40) ? dup2(w_cua[i]) : dup2(b_cua[i - 40]);
        for (int i = tid; i < 200; i += K2T) s_small[666 + i] = dup2(w_cu[i]);
        for (int i = tid; i < 22;  i += K2T) s_small[866 + i] = (i < 20) ? dup2(w_cla[i]) : dup2(b_cla[i - 20]);
        for (int i = tid; i < 200; i += K2T) s_small[888 + i] = dup2(w_cl[i]);
        for (int i = tid; i < 21;  i += K2T) s_small[1088 + i] = (i < 20) ? dup2(w_dua[256 + i]) : dup2(b_dua[0]);
        for (int i = tid; i < 100; i += K2T) s_small[1110 + i] = dup2(w_du[i]);
        for (int i = tid; i < 21;  i += K2T) s_small[1210 + i] = (i < 20) ? dup2(w_dla[256 + i]) : dup2(b_dla[0]);
        for (int i = tid; i < 100; i += K2T) s_small[1232 + i] = dup2(w_dl[i]);
        for (int i = tid; i < 210; i += K2T) s_small[1332 + i] = (i < 200) ? dup2(w_ugu[i]) : dup2(b_ugu[i - 200]);
        for (int i = tid; i < 200; i += K2T) s_small[1542 + i] = dup2(w_ucu[i]);
        for (int i = tid; i < 210; i += K2T) s_small[1742 + i] = (i < 200) ? dup2(w_ugl[i]) : dup2(b_ugl[i - 200]);
        for (int i = tid; i < 200; i += K2T) s_small[1952 + i] = dup2(w_ucl[i]);
    }
    __syncthreads();

    const int pair = blockIdx.x * K2T + tid;
    const int pix  = pair * 2;
    const int n    = pix >> 14;
    const int hw   = pix & (HWV - 1);
    const size_t vb = (size_t)n * HIDN * HWV + hw;
    const u64* hac = g_hacc + pair;

    u64 xu[10], xl[10];
#pragma unroll
    for (int i = 0; i < 10; i++) {
        xu[i] = *(const u64*)(g_xhu + vb + (size_t)i * HWV);
        xl[i] = *(const u64*)(g_xhl + vb + (size_t)i * HWV);
    }

    u64 dpl[10];
    {
        u64 tt[20];
#pragma unroll
        for (int o = 0; o < 20; o++) {
            u64 a = hac[(size_t)o * NPAIR];
            const u64* wr = s_small + o * 20;
#pragma unroll
            for (int k = 0; k < 10; k += 2) {
                uu2 w = lds2(wr + k);
                a = ffma2(xu[k], w.x, a);
                a = ffma2(xu[k + 1], w.y, a);
            }
#pragma unroll
            for (int k = 0; k < 10; k += 2) {
                uu2 w = lds2(wr + 10 + k);
                a = ffma2(xl[k], w.x, a);
                a = ffma2(xl[k + 1], w.y, a);
            }
            tt[o] = relu2(a);
        }
#pragma unroll
        for (int o = 0; o < 10; o++) {
            u64 a = 0ULL, b = 0ULL;
#pragma unroll
            for (int i = 0; i < 10; i += 2) {
                uu2 wa = lds2(s_small + 400 + o * 10 + i);
                uu2 wb = lds2(s_small + 500 + o * 10 + i);
                a = ffma2(tt[i],      wa.x, a);
                a = ffma2(tt[i + 1],  wa.y, a);
                b = ffma2(tt[10 + i], wb.x, b);
                b = ffma2(tt[11 + i], wb.y, b);
            }
            s_dpu[tid * 11 + o] = relu2(a);
            dpl[o] = relu2(b);
        }
    }
    u64 agu, agl;
    {
        u64 a = s_small[620], b = s_small[621];
#pragma unroll
        for (int i = 0; i < 10; i += 2) {
            uu2 wa = lds2(s_small + 600 + i);
            uu2 wb = lds2(s_small + 610 + i);
            a = ffma2(xu[i], wa.x, a);
            a = ffma2(xu[i + 1], wa.y, a);
            b = ffma2(xl[i], wb.x, b);
            b = ffma2(xl[i + 1], wb.y, b);
        }
        agu = sigmoid2(a);
        agl = sigmoid2(b);
    }

    u64 xfv[10];
#pragma unroll
    for (int i = 0; i < 10; i++) xfv[i] = *(const u64*)(g_xf + vb + (size_t)i * HWV);

    // ================= U half =================
    {
        u64 msg[10];
#pragma unroll
        for (int i = 0; i < 10; i++) msg[i] = 0ULL;
#pragma unroll
        for (int pp = 0; pp < 4; pp++) {
            u64 xv[10];
            const float* xpp = g_xp + ((size_t)(pp * NIMG + n) * HIDN) * HWV + hw;
#pragma unroll
            for (int i = 0; i < 10; i++) xv[i] = *(const u64*)(xpp + (size_t)i * HWV);
            u64 s = s_small[662 + pp];
#pragma unroll
            for (int i = 0; i < 10; i += 2) {
                uu2 w = lds2(s_small + 622 + pp * 10 + i);
                s = ffma2(xv[i], w.x, s);
                s = ffma2(xv[i + 1], w.y, s);
            }
            u64 ca = sigmoid2(s);
#pragma unroll
            for (int i = 0; i < 10; i++) msg[i] = ffma2(xv[i], ca, msg[i]);
        }
        u64 m[10];
#pragma unroll
        for (int o = 0; o < 10; o++) {
            u64 a = 0ULL;
            const u64* wr = s_small + 666 + o * 20;
#pragma unroll
            for (int i = 0; i < 10; i += 2) {
                uu2 wa = lds2(wr + i);
                uu2 wb = lds2(wr + 10 + i);
                a = ffma2(xu[i],  wa.x, a);
                a = ffma2(xu[i + 1], wa.y, a);
                a = ffma2(msg[i], wb.x, a);
                a = ffma2(msg[i + 1], wb.y, a);
            }
            m[o] = relu2(a);
            m[o] = ffma2(dpl[o], agl, m[o]);
            m[o] = ffma2(xu[o],  agu, m[o]);
        }
        u64 attu;
        {
            u64 s = fadd2(hac[(size_t)20 * NPAIR], s_small[1108]);
#pragma unroll
            for (int i = 0; i < 10; i += 2) {
                uu2 wa = lds2(s_small + 1088 + i);
                uu2 wb = lds2(s_small + 1098 + i);
                s = ffma2(xfv[i], wa.x, s);
                s = ffma2(xfv[i + 1], wa.y, s);
                s = ffma2(xu[i],  wb.x, s);
                s = ffma2(xu[i + 1], wb.y, s);
            }
            attu = sigmoid2(s);
        }
        *(u64*)(out + OUT_ATTU + (size_t)n * HWV + hw) = attu;
        {
            u64 xfa[10];
#pragma unroll
            for (int i = 0; i < 10; i++) xfa[i] = fmul2(xfv[i], attu);
#pragma unroll
            for (int o = 0; o < 10; o++) {
                u64 a = 0ULL;
#pragma unroll
                for (int i = 0; i < 10; i += 2) {
                    uu2 w = lds2(s_small + 1110 + o * 10 + i);
                    a = ffma2(xfa[i], w.x, a);
                    a = ffma2(xfa[i + 1], w.y, a);
                }
                m[o] = fadd2(m[o], relu2(a));
            }
        }
#pragma unroll
        for (int o = 0; o < 10; o++) {
            u64 g  = s_small[1532 + o];
            u64 cd = 0ULL;
            const u64* wg = s_small + 1332 + o * 20;
            const u64* wc = s_small + 1542 + o * 20;
#pragma unroll
            for (int i = 0; i < 10; i += 2) {
                uu2 a1 = lds2(wg + i);
                uu2 a2 = lds2(wc + i);
                g  = ffma2(xu[i], a1.x, g);
                g  = ffma2(xu[i + 1], a1.y, g);
                cd = ffma2(xu[i], a2.x, cd);
                cd = ffma2(xu[i + 1], a2.y, cd);
            }
#pragma unroll
            for (int i = 0; i < 10; i += 2) {
                uu2 a1 = lds2(wg + 10 + i);
                uu2 a2 = lds2(wc + 10 + i);
                g  = ffma2(m[i], a1.x, g);
                g  = ffma2(m[i + 1], a1.y, g);
                cd = ffma2(m[i], a2.x, cd);
                cd = ffma2(m[i + 1], a2.y, cd);
            }
            g  = sigmoid2(g);
            cd = relu2(cd);
            u64 res = ffma2(g, fadd2(cd, neg2(xu[o])), xu[o]);
            *(u64*)(out + (size_t)(n * HIDN + o) * HWV + hw) = res;
        }
    }

    // ================= L half =================
    {
        u64 xlv[10], xf2[10];
#pragma unroll
        for (int i = 0; i < 10; i++) {
            xlv[i] = *(const u64*)(g_xhl + vb + (size_t)i * HWV);
            xf2[i] = *(const u64*)(g_xf  + vb + (size_t)i * HWV);
        }
        u64 msg[10];
#pragma unroll
        for (int i = 0; i < 10; i++) msg[i] = 0ULL;
#pragma unroll
        for (int pp = 0; pp < 2; pp++) {
            u64 xv[10];
            const float* xpp = g_xp + ((size_t)((4 + pp) * NIMG + n) * HIDN) * HWV + hw;
#pragma unroll
            for (int i = 0; i < 10; i++) xv[i] = *(const u64*)(xpp + (size_t)i * HWV);
            u64 s = s_small[886 + pp];
#pragma unroll
            for (int i = 0; i < 10; i += 2) {
                uu2 w = lds2(s_small + 866 + pp * 10 + i);
                s = ffma2(xv[i], w.x, s);
                s = ffma2(xv[i + 1], w.y, s);
            }
            u64 ca = sigmoid2(s);
#pragma unroll
            for (int i = 0; i < 10; i++) msg[i] = ffma2(xv[i], ca, msg[i]);
        }
        u64 m[10];
#pragma unroll
        for (int o = 0; o < 10; o++) {
            u64 a = 0ULL;
            const u64* wr = s_small + 888 + o * 20;
#pragma unroll
            for (int i = 0; i < 10; i += 2) {
                uu2 wa = lds2(wr + i);
                uu2 wb = lds2(wr + 10 + i);
                a = ffma2(xlv[i], wa.x, a);
                a = ffma2(xlv[i + 1], wa.y, a);
                a = ffma2(msg[i], wb.x, a);
                a = ffma2(msg[i + 1], wb.y, a);
            }
            m[o] = relu2(a);
            m[o] = ffma2(s_dpu[tid * 11 + o], agu, m[o]);
            m[o] = ffma2(xlv[o], agl, m[o]);
        }
        u64 attl;
        {
            u64 s = fadd2(hac[(size_t)21 * NPAIR], s_small[1230]);
#pragma unroll
            for (int i = 0; i < 10; i += 2) {
                uu2 wa = lds2(s_small + 1210 + i);
                uu2 wb = lds2(s_small + 1220 + i);
                s = ffma2(xf2[i], wa.x, s);
                s = ffma2(xf2[i + 1], wa.y, s);
                s = ffma2(xlv[i], wb.x, s);
                s = ffma2(xlv[i + 1], wb.y, s);
            }
            attl = sigmoid2(s);
        }
        *(u64*)(out + OUT_ATTL + (size_t)n * HWV + hw) = attl;
        {
            u64 xfa[10];
#pragma unroll
            for (int i = 0; i < 10; i++) xfa[i] = fmul2(xf2[i], attl);
#pragma unroll
            for (int o = 0; o < 10; o++) {
                u64 a = 0ULL;
#pragma unroll
                for (int i = 0; i < 10; i += 2) {
                    uu2 w = lds2(s_small + 1232 + o * 10 + i);
                    a = ffma2(xfa[i], w.x, a);
                    a = ffma2(xfa[i + 1], w.y, a);
                }
                m[o] = fadd2(m[o], relu2(a));
            }
        }
#pragma unroll
        for (int o = 0; o < 10; o++) {
            u64 g  = s_small[1942 + o];
            u64 cd = 0ULL;
            const u64* wg = s_small + 1742 + o * 20;
            const u64* wc = s_small + 1952 + o * 20;
#pragma unroll
            for (int i = 0; i < 10; i += 2) {
                uu2 a1 = lds2(wg + i);
                uu2 a2 = lds2(wc + i);
                g  = ffma2(xlv[i], a1.x, g);
                g  = ffma2(xlv[i + 1], a1.y, g);
                cd = ffma2(xlv[i], a2.x, cd);
                cd = ffma2(xlv[i + 1], a2.y, cd);
            }
#pragma unroll
            for (int i = 0; i < 10; i += 2) {
                uu2 a1 = lds2(wg + 10 + i);
                uu2 a2 = lds2(wc + 10 + i);
                g  = ffma2(m[i], a1.x, g);
                g  = ffma2(m[i + 1], a1.y, g);
                cd = ffma2(m[i], a2.x, cd);
                cd = ffma2(m[i + 1], a2.y, cd);
            }
            g  = sigmoid2(g);
            cd = relu2(cd);
            u64 res = ffma2(g, fadd2(cd, neg2(xlv[o])), xlv[o]);
            *(u64*)(out + OUT_XHL + (size_t)(n * HIDN + o) * HWV + hw) = res;
        }
    }
}

extern "C" void kernel_launch(void* const* d_in, const int* in_sizes, int n_in,
                              void* d_out, int out_size) {
    cudaFuncSetAttribute(k1t_kernel, cudaFuncAttributeMaxDynamicSharedMemorySize,
                         K1_SMEM_BYTES);
    k1t_kernel<<<128, 256, K1_SMEM_BYTES>>>((const float*)d_in[0], (const float*)d_in[5],
                                            (const float*)d_in[15], (const float*)d_in[18]);
    P27 p;
    for (int i = 0; i < 27; i++) p.a[i] = (const float*)d_in[i];
    p.out = (float*)d_out;
    k2_kernel<<<512, K2T>>>(p);
}